// round 1
// baseline (speedup 1.0000x reference)
#include <cuda_runtime.h>
#include <cstdint>

// Problem constants (from reference setup_inputs)
#define N_MAX 100000
#define E_MAX 1600000
#define D_IN  256
#define H_DIM 128

// ---------------- scratch (device globals; no allocation allowed) ----------
__device__ float g_xw  [(size_t)N_MAX * H_DIM];   // x @ W1          (51.2 MB)
__device__ float g_agg1[(size_t)N_MAX * H_DIM];   // layer-1 agg     (51.2 MB)
__device__ float g_dinv[N_MAX];
__device__ int   g_deg [N_MAX];
__device__ float g_s   [N_MAX];                   // relu(h) . W2
__device__ int   g_is64;                          // edge_index dtype flag

// ---------------- edge index dtype detection -------------------------------
// jnp.int64 request may materialize as int32 (jax x64 disabled) or int64.
// For int64 with values in [0, 1e5), every odd 32-bit word is 0.
__global__ void k_detect(const int* __restrict__ ei_words) {
    if (blockIdx.x == 0 && threadIdx.x == 0) {
        int is64 = 1;
        for (int i = 1; i < 128; i += 2)
            if (ei_words[i] != 0) { is64 = 0; break; }
        g_is64 = is64;
    }
}

__device__ __forceinline__ int load_edge(const void* ei, int is64, size_t idx) {
    if (is64) return (int)((const long long*)ei)[idx];
    return ((const int*)ei)[idx];
}

// ---------------- degree / norm --------------------------------------------
__global__ void k_zero_deg(int N) {
    int i = blockIdx.x * blockDim.x + threadIdx.x;
    if (i < N) g_deg[i] = 0;
}

__global__ void k_hist(const void* __restrict__ ei, int E) {
    int e = blockIdx.x * blockDim.x + threadIdx.x;
    if (e < E) {
        int dst = load_edge(ei, g_is64, (size_t)E + e);
        atomicAdd(&g_deg[dst], 1);
    }
}

__global__ void k_dinv(int N) {
    int i = blockIdx.x * blockDim.x + threadIdx.x;
    if (i < N) g_dinv[i] = rsqrtf((float)(g_deg[i] + 1));  // +1 self-loop
}

// ---------------- SGEMM: g_xw = x[N,256] @ W1[256,128] ---------------------
// 128x128 tile per block, BK=8, 256 threads, 8x8 micro-tile per thread.
__global__ __launch_bounds__(256) void k_sgemm(const float* __restrict__ A,
                                               const float* __restrict__ B,
                                               int M) {
    __shared__ float As[8][128];
    __shared__ float Bs[8][128];
    int tid  = threadIdx.x;
    int row0 = blockIdx.x * 128;
    int tx = tid & 15, ty = tid >> 4;

    float acc[8][8];
#pragma unroll
    for (int i = 0; i < 8; i++)
#pragma unroll
        for (int j = 0; j < 8; j++) acc[i][j] = 0.0f;

    int a_row = tid >> 1;
    int a_k   = (tid & 1) * 4;
    int b_k   = tid >> 5;
    int b_c   = (tid & 31) * 4;

    for (int kb = 0; kb < D_IN; kb += 8) {
        float4 av = make_float4(0.f, 0.f, 0.f, 0.f);
        int gr = row0 + a_row;
        if (gr < M)
            av = *(const float4*)(A + (size_t)gr * D_IN + kb + a_k);
        As[a_k + 0][a_row] = av.x;
        As[a_k + 1][a_row] = av.y;
        As[a_k + 2][a_row] = av.z;
        As[a_k + 3][a_row] = av.w;
        *(float4*)(&Bs[b_k][b_c]) =
            *(const float4*)(B + (size_t)(kb + b_k) * H_DIM + b_c);
        __syncthreads();

#pragma unroll
        for (int kk = 0; kk < 8; kk++) {
            float a[8], b[8];
            *(float4*)(a)     = *(float4*)(&As[kk][ty * 8]);
            *(float4*)(a + 4) = *(float4*)(&As[kk][ty * 8 + 4]);
            *(float4*)(b)     = *(float4*)(&Bs[kk][tx * 8]);
            *(float4*)(b + 4) = *(float4*)(&Bs[kk][tx * 8 + 4]);
#pragma unroll
            for (int i = 0; i < 8; i++)
#pragma unroll
                for (int j = 0; j < 8; j++)
                    acc[i][j] += a[i] * b[j];
        }
        __syncthreads();
    }

#pragma unroll
    for (int i = 0; i < 8; i++) {
        int gr = row0 + ty * 8 + i;
        if (gr < M) {
            float* dst = &g_xw[(size_t)gr * H_DIM + tx * 8];
            *(float4*)(dst)     = make_float4(acc[i][0], acc[i][1], acc[i][2], acc[i][3]);
            *(float4*)(dst + 4) = make_float4(acc[i][4], acc[i][5], acc[i][6], acc[i][7]);
        }
    }
}

// ---------------- layer-1 aggregation --------------------------------------
// Self-loop term initializes g_agg1 (full overwrite; no memset needed).
__global__ void k_init_agg1(int N) {
    int t = blockIdx.x * blockDim.x + threadIdx.x;
    if (t >= N * 32) return;
    int v = t >> 5;
    int q = (t & 31) * 4;
    float d  = g_dinv[v];
    float d2 = d * d;
    float4 x4 = *(const float4*)&g_xw[(size_t)v * H_DIM + q];
    x4.x *= d2; x4.y *= d2; x4.z *= d2; x4.w *= d2;
    *(float4*)&g_agg1[(size_t)v * H_DIM + q] = x4;
}

// One warp per edge: gather xw[src] (128 floats), scale, vector-red into agg1[dst].
__global__ __launch_bounds__(256) void k_agg1_edges(const void* __restrict__ ei, int E) {
    int gid  = blockIdx.x * blockDim.x + threadIdx.x;
    int e    = gid >> 5;
    int lane = gid & 31;
    if (e >= E) return;
    int is64 = g_is64;
    int src = load_edge(ei, is64, (size_t)e);
    int dst = load_edge(ei, is64, (size_t)E + e);
    float norm = g_dinv[src] * g_dinv[dst];
    float4 v = *(const float4*)&g_xw[(size_t)src * H_DIM + lane * 4];
    v.x *= norm; v.y *= norm; v.z *= norm; v.w *= norm;
    float* addr = &g_agg1[(size_t)dst * H_DIM + lane * 4];
    unsigned long long gaddr = (unsigned long long)__cvta_generic_to_global(addr);
    asm volatile("red.global.add.v4.f32 [%0], {%1,%2,%3,%4};"
                 :: "l"(gaddr), "f"(v.x), "f"(v.y), "f"(v.z), "f"(v.w)
                 : "memory");
}

// ---------------- relu + dot with W2, init output with self-loop -----------
__global__ void k_relu_dot(const float* __restrict__ b1,
                           const float* __restrict__ W2,
                           const float* __restrict__ b2,
                           float* __restrict__ out, int N) {
    int gid  = blockIdx.x * blockDim.x + threadIdx.x;
    int v    = gid >> 5;
    int lane = gid & 31;
    if (v >= N) return;
    int q = lane * 4;
    float4 a  = *(const float4*)&g_agg1[(size_t)v * H_DIM + q];
    float4 bb = *(const float4*)&b1[q];
    float4 w  = *(const float4*)&W2[q];
    float acc = fmaxf(a.x + bb.x, 0.f) * w.x
              + fmaxf(a.y + bb.y, 0.f) * w.y
              + fmaxf(a.z + bb.z, 0.f) * w.z
              + fmaxf(a.w + bb.w, 0.f) * w.w;
#pragma unroll
    for (int off = 16; off; off >>= 1)
        acc += __shfl_xor_sync(0xffffffffu, acc, off);
    if (lane == 0) {
        g_s[v] = acc;
        float d = g_dinv[v];
        out[v] = d * d * acc + b2[0];   // self-loop + bias
    }
}

// ---------------- layer-2 scalar aggregation -------------------------------
__global__ void k_agg2_edges(const void* __restrict__ ei,
                             float* __restrict__ out, int E) {
    int e = blockIdx.x * blockDim.x + threadIdx.x;
    if (e >= E) return;
    int is64 = g_is64;
    int src = load_edge(ei, is64, (size_t)e);
    int dst = load_edge(ei, is64, (size_t)E + e);
    float val = g_dinv[src] * g_dinv[dst] * g_s[src];
    atomicAdd(&out[dst], val);
}

// ---------------- launch ----------------------------------------------------
extern "C" void kernel_launch(void* const* d_in, const int* in_sizes, int n_in,
                              void* d_out, int out_size) {
    const float* x  = (const float*)d_in[0];
    const void*  ei = d_in[1];
    const float* W1 = (const float*)d_in[2];
    const float* b1 = (const float*)d_in[3];
    const float* W2 = (const float*)d_in[4];
    const float* b2 = (const float*)d_in[5];
    float* out = (float*)d_out;

    int N = in_sizes[0] / D_IN;
    int E = in_sizes[1] / 2;

    k_detect<<<1, 32>>>((const int*)ei);
    k_zero_deg<<<(N + 255) / 256, 256>>>(N);
    k_hist<<<(E + 255) / 256, 256>>>(ei, E);
    k_dinv<<<(N + 255) / 256, 256>>>(N);
    k_sgemm<<<(N + 127) / 128, 256>>>(x, W1, N);
    k_init_agg1<<<(N * 32 + 255) / 256, 256>>>(N);
    k_agg1_edges<<<(E * 32 + 255) / 256, 256>>>(ei, E);
    k_relu_dot<<<(N * 32 + 255) / 256, 256>>>(b1, W2, b2, out, N);
    k_agg2_edges<<<(E + 255) / 256, 256>>>(ei, out, E);
}

// round 2
// speedup vs baseline: 1.1884x; 1.1884x over previous
#include <cuda_runtime.h>
#include <cstdint>

#define N_MAX 100000
#define E_MAX 1600000
#define D_IN  256
#define H_DIM 128

typedef unsigned long long ull;

// ---------------- scratch ---------------------------------------------------
__device__ float g_xw  [(size_t)N_MAX * H_DIM];   // x @ W1 (51.2 MB)
__device__ float g_dinv[N_MAX];
__device__ int   g_deg [N_MAX];
__device__ int   g_rowptr[N_MAX + 1];
__device__ int   g_cur [N_MAX];
__device__ int   g_ssrc[E_MAX];                   // srcs sorted by dst
__device__ float g_coef[E_MAX];                   // dinv[src] per sorted edge
__device__ float g_s   [N_MAX];                   // relu(h1) . W2
__device__ int   g_is64;

// ---------------- edge dtype detection -------------------------------------
__global__ void k_detect(const int* __restrict__ ei_words) {
    if (threadIdx.x == 0) {
        int is64 = 1;
        for (int i = 1; i < 128; i += 2)
            if (ei_words[i] != 0) { is64 = 0; break; }
        g_is64 = is64;
    }
}

__device__ __forceinline__ int load_edge(const void* ei, int is64, size_t idx) {
    if (is64) return (int)((const long long*)ei)[idx];
    return ((const int*)ei)[idx];
}

// ---------------- degree / norm --------------------------------------------
__global__ void k_zero_deg(int N) {
    int i = blockIdx.x * blockDim.x + threadIdx.x;
    if (i < N) g_deg[i] = 0;
}

__global__ void k_hist(const void* __restrict__ ei, int E) {
    int e = blockIdx.x * blockDim.x + threadIdx.x;
    if (e < E) atomicAdd(&g_deg[load_edge(ei, g_is64, (size_t)E + e)], 1);
}

__global__ void k_dinv(int N) {
    int i = blockIdx.x * blockDim.x + threadIdx.x;
    if (i < N) g_dinv[i] = rsqrtf((float)(g_deg[i] + 1));
}

// ---------------- single-block exclusive scan (4 elems/thread) -------------
__global__ void k_scan(int N) {
    __shared__ int sh[1024];
    int t = threadIdx.x;
    int carry = 0;
    for (int base = 0; base < N; base += 4096) {
        int i0 = base + t * 4;
        int v0 = (i0 + 0 < N) ? g_deg[i0 + 0] : 0;
        int v1 = (i0 + 1 < N) ? g_deg[i0 + 1] : 0;
        int v2 = (i0 + 2 < N) ? g_deg[i0 + 2] : 0;
        int v3 = (i0 + 3 < N) ? g_deg[i0 + 3] : 0;
        int s = v0 + v1 + v2 + v3;
        sh[t] = s;
        __syncthreads();
#pragma unroll
        for (int off = 1; off < 1024; off <<= 1) {
            int add = (t >= off) ? sh[t - off] : 0;
            __syncthreads();
            sh[t] += add;
            __syncthreads();
        }
        int excl = carry + sh[t] - s;
        if (i0 + 0 < N) { g_rowptr[i0 + 0] = excl; g_cur[i0 + 0] = excl; excl += v0; }
        if (i0 + 1 < N) { g_rowptr[i0 + 1] = excl; g_cur[i0 + 1] = excl; excl += v1; }
        if (i0 + 2 < N) { g_rowptr[i0 + 2] = excl; g_cur[i0 + 2] = excl; excl += v2; }
        if (i0 + 3 < N) { g_rowptr[i0 + 3] = excl; g_cur[i0 + 3] = excl; excl += v3; }
        int tot = sh[1023];
        carry += tot;
        __syncthreads();
    }
    if (t == 0) g_rowptr[N] = carry;
}

// ---------------- counting-sort scatter ------------------------------------
__global__ void k_scatter(const void* __restrict__ ei, int E) {
    int e = blockIdx.x * blockDim.x + threadIdx.x;
    if (e >= E) return;
    int is64 = g_is64;
    int src = load_edge(ei, is64, (size_t)e);
    int dst = load_edge(ei, is64, (size_t)E + e);
    int pos = atomicAdd(&g_cur[dst], 1);
    g_ssrc[pos] = src;
    g_coef[pos] = g_dinv[src];
}

// ---------------- SGEMM with packed fma.rn.f32x2 ---------------------------
__device__ __forceinline__ void fma2(ull& d, ull a, ull b) {
    asm("fma.rn.f32x2 %0, %1, %2, %0;" : "+l"(d) : "l"(a), "l"(b));
}
__device__ __forceinline__ ull dupf(float x) {
    ull r;
    asm("mov.b64 %0, {%1, %1};" : "=l"(r) : "f"(x));
    return r;
}

__global__ __launch_bounds__(256) void k_sgemm(const float* __restrict__ A,
                                               const float* __restrict__ B,
                                               int M) {
    __shared__ float As[8][128];
    __shared__ float Bs[8][128];
    int tid  = threadIdx.x;
    int row0 = blockIdx.x * 128;
    int tx = tid & 15, ty = tid >> 4;

    ull acc2[8][4];
#pragma unroll
    for (int i = 0; i < 8; i++)
#pragma unroll
        for (int p = 0; p < 4; p++) acc2[i][p] = 0ull;

    int a_row = tid >> 1;
    int a_k   = (tid & 1) * 4;
    int b_k   = tid >> 5;
    int b_c   = (tid & 31) * 4;

    for (int kb = 0; kb < D_IN; kb += 8) {
        float4 av = make_float4(0.f, 0.f, 0.f, 0.f);
        int gr = row0 + a_row;
        if (gr < M)
            av = *(const float4*)(A + (size_t)gr * D_IN + kb + a_k);
        As[a_k + 0][a_row] = av.x;
        As[a_k + 1][a_row] = av.y;
        As[a_k + 2][a_row] = av.z;
        As[a_k + 3][a_row] = av.w;
        *(float4*)(&Bs[b_k][b_c]) =
            *(const float4*)(B + (size_t)(kb + b_k) * H_DIM + b_c);
        __syncthreads();

#pragma unroll
        for (int kk = 0; kk < 8; kk++) {
            float a[8];
            *(float4*)(a)     = *(float4*)(&As[kk][ty * 8]);
            *(float4*)(a + 4) = *(float4*)(&As[kk][ty * 8 + 4]);
            ulonglong2 b01 = *(const ulonglong2*)(&Bs[kk][tx * 8]);
            ulonglong2 b23 = *(const ulonglong2*)(&Bs[kk][tx * 8 + 4]);
            ull bp0 = b01.x, bp1 = b01.y, bp2 = b23.x, bp3 = b23.y;
#pragma unroll
            for (int i = 0; i < 8; i++) {
                ull ad = dupf(a[i]);
                fma2(acc2[i][0], ad, bp0);
                fma2(acc2[i][1], ad, bp1);
                fma2(acc2[i][2], ad, bp2);
                fma2(acc2[i][3], ad, bp3);
            }
        }
        __syncthreads();
    }

#pragma unroll
    for (int i = 0; i < 8; i++) {
        int gr = row0 + ty * 8 + i;
        if (gr < M) {
            float* dst = &g_xw[(size_t)gr * H_DIM + tx * 8];
            *(ulonglong2*)(dst)     = make_ulonglong2(acc2[i][0], acc2[i][1]);
            *(ulonglong2*)(dst + 4) = make_ulonglong2(acc2[i][2], acc2[i][3]);
        }
    }
}

// ---------------- fused layer-1 aggregate + relu + W2 dot ------------------
// warp per dst node; lane owns 4 of 128 hidden dims.
__global__ __launch_bounds__(256) void k_fused1(const float* __restrict__ b1,
                                                const float* __restrict__ W2,
                                                int N) {
    int gid  = blockIdx.x * blockDim.x + threadIdx.x;
    int v    = gid >> 5;
    int lane = gid & 31;
    if (v >= N) return;
    int beg = g_rowptr[v], end = g_rowptr[v + 1];
    int q = lane * 4;
    float4 acc = make_float4(0.f, 0.f, 0.f, 0.f);
    for (int j = beg; j < end; j++) {
        int   src = g_ssrc[j];     // uniform across warp -> broadcast
        float c   = g_coef[j];
        float4 xv = *(const float4*)&g_xw[(size_t)src * H_DIM + q];
        acc.x = fmaf(c, xv.x, acc.x);
        acc.y = fmaf(c, xv.y, acc.y);
        acc.z = fmaf(c, xv.z, acc.z);
        acc.w = fmaf(c, xv.w, acc.w);
    }
    float d  = g_dinv[v];
    float d2 = d * d;
    float4 self = *(const float4*)&g_xw[(size_t)v * H_DIM + q];
    float4 bb   = *(const float4*)&b1[q];
    float4 w    = *(const float4*)&W2[q];
    float sum = fmaxf(d * acc.x + d2 * self.x + bb.x, 0.f) * w.x
              + fmaxf(d * acc.y + d2 * self.y + bb.y, 0.f) * w.y
              + fmaxf(d * acc.z + d2 * self.z + bb.z, 0.f) * w.z
              + fmaxf(d * acc.w + d2 * self.w + bb.w, 0.f) * w.w;
#pragma unroll
    for (int off = 16; off; off >>= 1)
        sum += __shfl_xor_sync(0xffffffffu, sum, off);
    if (lane == 0) g_s[v] = sum;
}

// ---------------- layer-2: warp per dst node, CSR reduce -------------------
__global__ __launch_bounds__(256) void k_out(const float* __restrict__ b2,
                                             float* __restrict__ out, int N) {
    int gid  = blockIdx.x * blockDim.x + threadIdx.x;
    int v    = gid >> 5;
    int lane = gid & 31;
    if (v >= N) return;
    int beg = g_rowptr[v], end = g_rowptr[v + 1];
    float acc = 0.f;
    for (int j = beg + lane; j < end; j += 32)
        acc += g_coef[j] * g_s[g_ssrc[j]];
#pragma unroll
    for (int off = 16; off; off >>= 1)
        acc += __shfl_xor_sync(0xffffffffu, acc, off);
    if (lane == 0) {
        float d = g_dinv[v];
        out[v] = d * acc + d * d * g_s[v] + b2[0];
    }
}

// ---------------- launch ----------------------------------------------------
extern "C" void kernel_launch(void* const* d_in, const int* in_sizes, int n_in,
                              void* d_out, int out_size) {
    const float* x  = (const float*)d_in[0];
    const void*  ei = d_in[1];
    const float* W1 = (const float*)d_in[2];
    const float* b1 = (const float*)d_in[3];
    const float* W2 = (const float*)d_in[4];
    const float* b2 = (const float*)d_in[5];
    float* out = (float*)d_out;

    int N = in_sizes[0] / D_IN;
    int E = in_sizes[1] / 2;

    k_detect<<<1, 32>>>((const int*)ei);
    k_zero_deg<<<(N + 255) / 256, 256>>>(N);
    k_hist<<<(E + 255) / 256, 256>>>(ei, E);
    k_dinv<<<(N + 255) / 256, 256>>>(N);
    k_scan<<<1, 1024>>>(N);
    k_scatter<<<(E + 255) / 256, 256>>>(ei, E);
    k_sgemm<<<(N + 127) / 128, 256>>>(x, W1, N);
    k_fused1<<<(N * 32 + 255) / 256, 256>>>(b1, W2, N);
    k_out<<<(N * 32 + 255) / 256, 256>>>(b2, out, N);
}

// round 8
// speedup vs baseline: 2.0324x; 1.7102x over previous
#include <cuda_runtime.h>
#include <cuda_bf16.h>
#include <mma.h>
#include <cstdint>

using namespace nvcuda;

#define N_MAX 100000
#define N_PAD 100096              // rows padded to multiple of 128 for wmma stores
#define E_MAX 1600000
#define D_IN  256
#define H_DIM 128

// ---------------- scratch ---------------------------------------------------
__device__ float g_xw  [(size_t)N_PAD * H_DIM];   // x @ W1 (padded rows)
__device__ float g_dinv[N_MAX];
__device__ int   g_deg [N_MAX];
__device__ int   g_rowptr[N_MAX + 1];
__device__ int   g_cur [N_MAX];
__device__ int   g_part[256];
__device__ int   g_ssrc[E_MAX];
__device__ float g_coef[E_MAX];
__device__ float g_s   [N_MAX];
__device__ int   g_is64;
__device__ __align__(16) __nv_bfloat16 g_wh[D_IN * H_DIM];  // W1 hi, [k][n]
__device__ __align__(16) __nv_bfloat16 g_wl[D_IN * H_DIM];  // W1 lo, [k][n]

// ---------------- edge dtype detection -------------------------------------
__global__ void k_detect(const int* __restrict__ ei_words) {
    if (threadIdx.x == 0) {
        int is64 = 1;
        for (int i = 1; i < 128; i += 2)
            if (ei_words[i] != 0) { is64 = 0; break; }
        g_is64 = is64;
    }
}
__device__ __forceinline__ int load_edge(const void* ei, int is64, size_t idx) {
    if (is64) return (int)((const long long*)ei)[idx];
    return ((const int*)ei)[idx];
}

// ---------------- W1 bf16 hi/lo split (native k x n layout) ----------------
__global__ void k_prep_w(const float* __restrict__ W1) {
    int i = blockIdx.x * blockDim.x + threadIdx.x;
    if (i >= D_IN * H_DIM) return;
    float v = W1[i];
    __nv_bfloat16 h = __float2bfloat16(v);
    g_wh[i] = h;
    g_wl[i] = __float2bfloat16(v - __bfloat162float(h));
}

// ---------------- degree / norm --------------------------------------------
__global__ void k_zero_deg(int N) {
    int i = blockIdx.x * blockDim.x + threadIdx.x;
    if (i < N) g_deg[i] = 0;
}
__global__ void k_hist(const void* __restrict__ ei, int E) {
    int e = blockIdx.x * blockDim.x + threadIdx.x;
    if (e < E) atomicAdd(&g_deg[load_edge(ei, g_is64, (size_t)E + e)], 1);
}
__global__ void k_dinv(int N) {
    int i = blockIdx.x * blockDim.x + threadIdx.x;
    if (i < N) g_dinv[i] = rsqrtf((float)(g_deg[i] + 1));
}

// ---------------- multi-block scan -----------------------------------------
__global__ void k_scan1(int N) {
    __shared__ int sh[256];
    int b = blockIdx.x, t = threadIdx.x;
    int i0 = b * 1024 + t * 4;
    int v0 = (i0 + 0 < N) ? g_deg[i0 + 0] : 0;
    int v1 = (i0 + 1 < N) ? g_deg[i0 + 1] : 0;
    int v2 = (i0 + 2 < N) ? g_deg[i0 + 2] : 0;
    int v3 = (i0 + 3 < N) ? g_deg[i0 + 3] : 0;
    int s = v0 + v1 + v2 + v3;
    sh[t] = s;
    __syncthreads();
#pragma unroll
    for (int off = 1; off < 256; off <<= 1) {
        int add = (t >= off) ? sh[t - off] : 0;
        __syncthreads();
        sh[t] += add;
        __syncthreads();
    }
    int excl = sh[t] - s;
    if (i0 + 0 < N) { g_rowptr[i0 + 0] = excl; excl += v0; }
    if (i0 + 1 < N) { g_rowptr[i0 + 1] = excl; excl += v1; }
    if (i0 + 2 < N) { g_rowptr[i0 + 2] = excl; excl += v2; }
    if (i0 + 3 < N) { g_rowptr[i0 + 3] = excl; }
    if (t == 255) g_part[b] = sh[255];
}
__global__ void k_scan2(int nb, int N) {
    __shared__ int sh[128];
    int t = threadIdx.x;
    int v = (t < nb) ? g_part[t] : 0;
    sh[t] = v;
    __syncthreads();
#pragma unroll
    for (int off = 1; off < 128; off <<= 1) {
        int add = (t >= off) ? sh[t - off] : 0;
        __syncthreads();
        sh[t] += add;
        __syncthreads();
    }
    if (t < nb) g_part[t] = sh[t] - v;
    if (t == 127) g_rowptr[N] = sh[127];
}
__global__ void k_scan3(int N) {
    int i = blockIdx.x * blockDim.x + threadIdx.x;
    if (i < N) {
        int r = g_rowptr[i] + g_part[i >> 10];
        g_rowptr[i] = r;
        g_cur[i] = r;
    }
}

// ---------------- counting-sort scatter ------------------------------------
__global__ void k_scatter(const void* __restrict__ ei, int E) {
    int e = blockIdx.x * blockDim.x + threadIdx.x;
    if (e >= E) return;
    int is64 = g_is64;
    int src = load_edge(ei, is64, (size_t)e);
    int dst = load_edge(ei, is64, (size_t)E + e);
    int pos = atomicAdd(&g_cur[dst], 1);
    g_ssrc[pos] = src;
    g_coef[pos] = g_dinv[src];
}

// ---------------- wmma bf16-split GEMM: g_xw = x @ W1 ----------------------
// CTA tile 128x128, K chunks of 64. 8 warps in 2x4; warp tile 64x32.
// Splits: hi*hi + hi*lo + lo*hi (fp32 accum); lo*lo dropped (~2^-18).
#define LDA 72      // 64 + 8 pad (bf16 elems)
#define LDB 136     // 128 + 8 pad
#define SM_AHI 0
#define SM_ALO (SM_AHI + 128 * LDA * 2)
#define SM_BHI (SM_ALO + 128 * LDA * 2)
#define SM_BLO (SM_BHI + 64 * LDB * 2)
#define SM_TOTAL (SM_BLO + 64 * LDB * 2)

__device__ __forceinline__ uint32_t pk2(__nv_bfloat16 a, __nv_bfloat16 b) {
    __nv_bfloat162 t(a, b);
    return *(uint32_t*)&t;
}

__global__ __launch_bounds__(256) void k_gemm(const float* __restrict__ A, int M) {
    extern __shared__ char sm[];
    __nv_bfloat16* As_hi = (__nv_bfloat16*)(sm + SM_AHI);
    __nv_bfloat16* As_lo = (__nv_bfloat16*)(sm + SM_ALO);
    __nv_bfloat16* Bs_hi = (__nv_bfloat16*)(sm + SM_BHI);
    __nv_bfloat16* Bs_lo = (__nv_bfloat16*)(sm + SM_BLO);

    int tid = threadIdx.x;
    int wid = tid >> 5;
    int wm = wid >> 2;          // 0..1 -> 64-row slab
    int wn = wid & 3;           // 0..3 -> 32-col slab
    int row0 = blockIdx.x * 128;

    wmma::fragment<wmma::accumulator, 16, 16, 16, float> acc[4][2];
#pragma unroll
    for (int i = 0; i < 4; i++)
#pragma unroll
        for (int j = 0; j < 2; j++) wmma::fill_fragment(acc[i][j], 0.0f);

    for (int c = 0; c < 4; c++) {
        int kb = c * 64;
        // stage A chunk [128 x 64] fp32 -> bf16 hi/lo
#pragma unroll
        for (int it = 0; it < 8; it++) {
            int f = it * 256 + tid;        // float4 index; 16 per row
            int r = f >> 4, c4 = f & 15;
            float4 v = make_float4(0.f, 0.f, 0.f, 0.f);
            int gr = row0 + r;
            if (gr < M) v = *(const float4*)(A + (size_t)gr * D_IN + kb + c4 * 4);
            __nv_bfloat16 h0 = __float2bfloat16(v.x);
            __nv_bfloat16 h1 = __float2bfloat16(v.y);
            __nv_bfloat16 h2 = __float2bfloat16(v.z);
            __nv_bfloat16 h3 = __float2bfloat16(v.w);
            __nv_bfloat16 l0 = __float2bfloat16(v.x - __bfloat162float(h0));
            __nv_bfloat16 l1 = __float2bfloat16(v.y - __bfloat162float(h1));
            __nv_bfloat16 l2 = __float2bfloat16(v.z - __bfloat162float(h2));
            __nv_bfloat16 l3 = __float2bfloat16(v.w - __bfloat162float(h3));
            int off = r * LDA + c4 * 4;
            *(uint2*)(As_hi + off) = make_uint2(pk2(h0, h1), pk2(h2, h3));
            *(uint2*)(As_lo + off) = make_uint2(pk2(l0, l1), pk2(l2, l3));
        }
        // stage B chunk [64 x 128] from prepped bf16 (k x n layout)
#pragma unroll
        for (int it = 0; it < 4; it++) {
            int g = it * 256 + tid;        // 8-elem group; 16 per row
            int k = g >> 4, n8 = g & 15;
            int src = (kb + k) * H_DIM + n8 * 8;
            int off = k * LDB + n8 * 8;
            *(uint4*)(Bs_hi + off) = *(const uint4*)(g_wh + src);
            *(uint4*)(Bs_lo + off) = *(const uint4*)(g_wl + src);
        }
        __syncthreads();

#pragma unroll
        for (int split = 0; split < 3; split++) {
            const __nv_bfloat16* Ap = (split == 2) ? As_lo : As_hi;
            const __nv_bfloat16* Bp = (split == 1) ? Bs_lo : Bs_hi;
#pragma unroll
            for (int kk = 0; kk < 4; kk++) {
                wmma::fragment<wmma::matrix_a, 16, 16, 16, __nv_bfloat16,
                               wmma::row_major> a[4];
                wmma::fragment<wmma::matrix_b, 16, 16, 16, __nv_bfloat16,
                               wmma::row_major> b[2];
#pragma unroll
                for (int i = 0; i < 4; i++)
                    wmma::load_matrix_sync(a[i],
                        Ap + (wm * 64 + i * 16) * LDA + kk * 16, LDA);
#pragma unroll
                for (int j = 0; j < 2; j++)
                    wmma::load_matrix_sync(b[j],
                        Bp + (kk * 16) * LDB + wn * 32 + j * 16, LDB);
#pragma unroll
                for (int i = 0; i < 4; i++)
#pragma unroll
                    for (int j = 0; j < 2; j++)
                        wmma::mma_sync(acc[i][j], a[i], b[j], acc[i][j]);
            }
        }
        __syncthreads();
    }

    // epilogue (rows padded to N_PAD; unguarded store is safe)
#pragma unroll
    for (int i = 0; i < 4; i++)
#pragma unroll
        for (int j = 0; j < 2; j++) {
            int gr = row0 + wm * 64 + i * 16;
            int gc = wn * 32 + j * 16;
            wmma::store_matrix_sync(&g_xw[(size_t)gr * H_DIM + gc],
                                    acc[i][j], H_DIM, wmma::mem_row_major);
        }
}

// ---------------- fused layer-1 aggregate + relu + W2 dot ------------------
__global__ __launch_bounds__(256) void k_fused1(const float* __restrict__ b1,
                                                const float* __restrict__ W2,
                                                int N) {
    int gid  = blockIdx.x * blockDim.x + threadIdx.x;
    int v    = gid >> 5;
    int lane = gid & 31;
    if (v >= N) return;
    int beg = g_rowptr[v], end = g_rowptr[v + 1];
    int q = lane * 4;
    float4 acc = make_float4(0.f, 0.f, 0.f, 0.f);
    for (int j = beg; j < end; j++) {
        int   src = g_ssrc[j];
        float c   = g_coef[j];
        float4 xv = *(const float4*)&g_xw[(size_t)src * H_DIM + q];
        acc.x = fmaf(c, xv.x, acc.x);
        acc.y = fmaf(c, xv.y, acc.y);
        acc.z = fmaf(c, xv.z, acc.z);
        acc.w = fmaf(c, xv.w, acc.w);
    }
    float d  = g_dinv[v];
    float d2 = d * d;
    float4 self = *(const float4*)&g_xw[(size_t)v * H_DIM + q];
    float4 bb   = *(const float4*)&b1[q];
    float4 w    = *(const float4*)&W2[q];
    float sum = fmaxf(d * acc.x + d2 * self.x + bb.x, 0.f) * w.x
              + fmaxf(d * acc.y + d2 * self.y + bb.y, 0.f) * w.y
              + fmaxf(d * acc.z + d2 * self.z + bb.z, 0.f) * w.z
              + fmaxf(d * acc.w + d2 * self.w + bb.w, 0.f) * w.w;
#pragma unroll
    for (int off = 16; off; off >>= 1)
        sum += __shfl_xor_sync(0xffffffffu, sum, off);
    if (lane == 0) g_s[v] = sum;
}

// ---------------- layer-2 ---------------------------------------------------
__global__ __launch_bounds__(256) void k_out(const float* __restrict__ b2,
                                             float* __restrict__ out, int N) {
    int gid  = blockIdx.x * blockDim.x + threadIdx.x;
    int v    = gid >> 5;
    int lane = gid & 31;
    if (v >= N) return;
    int beg = g_rowptr[v], end = g_rowptr[v + 1];
    float acc = 0.f;
    for (int j = beg + lane; j < end; j += 32)
        acc += g_coef[j] * g_s[g_ssrc[j]];
#pragma unroll
    for (int off = 16; off; off >>= 1)
        acc += __shfl_xor_sync(0xffffffffu, acc, off);
    if (lane == 0) {
        float d = g_dinv[v];
        out[v] = d * acc + d * d * g_s[v] + b2[0];
    }
}

// ---------------- launch ----------------------------------------------------
extern "C" void kernel_launch(void* const* d_in, const int* in_sizes, int n_in,
                              void* d_out, int out_size) {
    const float* x  = (const float*)d_in[0];
    const void*  ei = d_in[1];
    const float* W1 = (const float*)d_in[2];
    const float* b1 = (const float*)d_in[3];
    const float* W2 = (const float*)d_in[4];
    const float* b2 = (const float*)d_in[5];
    float* out = (float*)d_out;

    int N = in_sizes[0] / D_IN;
    int E = in_sizes[1] / 2;
    int nb = (N + 1023) / 1024;

    static int smem_set = 0;
    if (!smem_set) {
        cudaFuncSetAttribute(k_gemm, cudaFuncAttributeMaxDynamicSharedMemorySize,
                             SM_TOTAL);
        smem_set = 1;
    }

    k_detect<<<1, 32>>>((const int*)ei);
    k_prep_w<<<(D_IN * H_DIM + 255) / 256, 256>>>(W1);
    k_zero_deg<<<(N + 255) / 256, 256>>>(N);
    k_gemm<<<(N + 127) / 128, 256, SM_TOTAL>>>(x, N);
    k_hist<<<(E + 255) / 256, 256>>>(ei, E);
    k_dinv<<<(N + 255) / 256, 256>>>(N);
    k_scan1<<<nb, 256>>>(N);
    k_scan2<<<1, 128>>>(nb, N);
    k_scan3<<<(N + 255) / 256, 256>>>(N);
    k_scatter<<<(E + 255) / 256, 256>>>(ei, E);
    k_fused1<<<(N * 32 + 255) / 256, 256>>>(b1, W2, N);
    k_out<<<(N * 32 + 255) / 256, 256>>>(b2, out, N);
}

// round 11
// speedup vs baseline: 2.0959x; 1.0312x over previous
#include <cuda_runtime.h>
#include <cuda_bf16.h>
#include <cuda_fp16.h>
#include <mma.h>
#include <cstdint>

using namespace nvcuda;

#define N_MAX 100000
#define N_PAD 100096              // rows padded to multiple of 128
#define E_MAX 1600000
#define D_IN  256
#define H_DIM 128

// ---------------- scratch ---------------------------------------------------
__device__ __half g_xh [(size_t)N_PAD * H_DIM];   // x @ W1 (fp16, 25.6 MB)
__device__ float g_dinv[N_MAX];
__device__ int   g_deg [N_MAX];
__device__ int   g_rowptr[N_MAX + 1];
__device__ int   g_cur [N_MAX];
__device__ int   g_part[256];
__device__ int   g_ssrc[E_MAX];
__device__ float g_coef[E_MAX];
__device__ float g_s   [N_MAX];
__device__ int   g_is64;
__device__ __align__(16) __nv_bfloat16 g_wh[D_IN * H_DIM];  // W1 hi, [k][n]
__device__ __align__(16) __nv_bfloat16 g_wl[D_IN * H_DIM];  // W1 lo, [k][n]

// ---------------- edge dtype detection -------------------------------------
__global__ void k_detect(const int* __restrict__ ei_words) {
    if (threadIdx.x == 0) {
        int is64 = 1;
        for (int i = 1; i < 128; i += 2)
            if (ei_words[i] != 0) { is64 = 0; break; }
        g_is64 = is64;
    }
}
__device__ __forceinline__ int load_edge(const void* ei, int is64, size_t idx) {
    if (is64) return (int)((const long long*)ei)[idx];
    return ((const int*)ei)[idx];
}

// ---------------- W1 bf16 hi/lo split (native k x n layout) ----------------
__global__ void k_prep_w(const float* __restrict__ W1) {
    int i = blockIdx.x * blockDim.x + threadIdx.x;
    if (i >= D_IN * H_DIM) return;
    float v = W1[i];
    __nv_bfloat16 h = __float2bfloat16(v);
    g_wh[i] = h;
    g_wl[i] = __float2bfloat16(v - __bfloat162float(h));
}

// ---------------- degree / norm --------------------------------------------
__global__ void k_zero_deg(int N) {
    int i = blockIdx.x * blockDim.x + threadIdx.x;
    if (i < N) g_deg[i] = 0;
}
__global__ void k_hist(const void* __restrict__ ei, int E) {
    int e = blockIdx.x * blockDim.x + threadIdx.x;
    if (e < E) atomicAdd(&g_deg[load_edge(ei, g_is64, (size_t)E + e)], 1);
}
__global__ void k_dinv(int N) {
    int i = blockIdx.x * blockDim.x + threadIdx.x;
    if (i < N) g_dinv[i] = rsqrtf((float)(g_deg[i] + 1));
}

// ---------------- multi-block scan -----------------------------------------
__global__ void k_scan1(int N) {
    __shared__ int sh[256];
    int b = blockIdx.x, t = threadIdx.x;
    int i0 = b * 1024 + t * 4;
    int v0 = (i0 + 0 < N) ? g_deg[i0 + 0] : 0;
    int v1 = (i0 + 1 < N) ? g_deg[i0 + 1] : 0;
    int v2 = (i0 + 2 < N) ? g_deg[i0 + 2] : 0;
    int v3 = (i0 + 3 < N) ? g_deg[i0 + 3] : 0;
    int s = v0 + v1 + v2 + v3;
    sh[t] = s;
    __syncthreads();
#pragma unroll
    for (int off = 1; off < 256; off <<= 1) {
        int add = (t >= off) ? sh[t - off] : 0;
        __syncthreads();
        sh[t] += add;
        __syncthreads();
    }
    int excl = sh[t] - s;
    if (i0 + 0 < N) { g_rowptr[i0 + 0] = excl; excl += v0; }
    if (i0 + 1 < N) { g_rowptr[i0 + 1] = excl; excl += v1; }
    if (i0 + 2 < N) { g_rowptr[i0 + 2] = excl; excl += v2; }
    if (i0 + 3 < N) { g_rowptr[i0 + 3] = excl; }
    if (t == 255) g_part[b] = sh[255];
}
__global__ void k_scan2(int nb, int N) {
    __shared__ int sh[128];
    int t = threadIdx.x;
    int v = (t < nb) ? g_part[t] : 0;
    sh[t] = v;
    __syncthreads();
#pragma unroll
    for (int off = 1; off < 128; off <<= 1) {
        int add = (t >= off) ? sh[t - off] : 0;
        __syncthreads();
        sh[t] += add;
        __syncthreads();
    }
    if (t < nb) g_part[t] = sh[t] - v;
    if (t == 127) g_rowptr[N] = sh[127];
}
__global__ void k_scan3(int N) {
    int i = blockIdx.x * blockDim.x + threadIdx.x;
    if (i < N) {
        int r = g_rowptr[i] + g_part[i >> 10];
        g_rowptr[i] = r;
        g_cur[i] = r;
    }
}

// ---------------- counting-sort scatter ------------------------------------
__global__ void k_scatter(const void* __restrict__ ei, int E) {
    int e = blockIdx.x * blockDim.x + threadIdx.x;
    if (e >= E) return;
    int is64 = g_is64;
    int src = load_edge(ei, is64, (size_t)e);
    int dst = load_edge(ei, is64, (size_t)E + e);
    int pos = atomicAdd(&g_cur[dst], 1);
    g_ssrc[pos] = src;
    g_coef[pos] = g_dinv[src];
}

// ---------------- wmma bf16-split GEMM: g_xh = fp16(x @ W1) ----------------
// CTA tile 128x128, 512 threads = 16 warps in 4x4; warp tile 32x32.
// kk-outer fragment hoisting: each hi/lo fragment loaded once per kk,
// reused across the 3 splits (hi*hi + hi*lo + lo*hi; lo*lo dropped).
#define LDA 72      // 64 + 8 pad (bf16 elems)
#define LDB 136     // 128 + 8 pad
#define LDC 132     // 128 + 4 pad (fp32 elems, epilogue staging)
#define SM_AHI 0
#define SM_ALO (SM_AHI + 128 * LDA * 2)
#define SM_BHI (SM_ALO + 128 * LDA * 2)
#define SM_BLO (SM_BHI + 64 * LDB * 2)
#define SM_TOTAL (SM_BLO + 64 * LDB * 2)   // 71680; epilogue reuse needs 67584

__device__ __forceinline__ uint32_t pk2(__nv_bfloat16 a, __nv_bfloat16 b) {
    __nv_bfloat162 t(a, b);
    return *(uint32_t*)&t;
}

__global__ __launch_bounds__(512) void k_gemm(const float* __restrict__ A, int M) {
    extern __shared__ char sm[];
    __nv_bfloat16* As_hi = (__nv_bfloat16*)(sm + SM_AHI);
    __nv_bfloat16* As_lo = (__nv_bfloat16*)(sm + SM_ALO);
    __nv_bfloat16* Bs_hi = (__nv_bfloat16*)(sm + SM_BHI);
    __nv_bfloat16* Bs_lo = (__nv_bfloat16*)(sm + SM_BLO);

    int tid = threadIdx.x;
    int wid = tid >> 5;
    int wm = wid >> 2;          // 0..3 -> 32-row slab
    int wn = wid & 3;           // 0..3 -> 32-col slab
    int row0 = blockIdx.x * 128;

    wmma::fragment<wmma::accumulator, 16, 16, 16, float> acc[2][2];
#pragma unroll
    for (int i = 0; i < 2; i++)
#pragma unroll
        for (int j = 0; j < 2; j++) wmma::fill_fragment(acc[i][j], 0.0f);

    for (int c = 0; c < 4; c++) {
        int kb = c * 64;
        // stage A chunk [128 x 64] fp32 -> bf16 hi/lo  (2048 float4, 4 iters)
#pragma unroll
        for (int it = 0; it < 4; it++) {
            int f = it * 512 + tid;
            int r = f >> 4, c4 = f & 15;
            float4 v = make_float4(0.f, 0.f, 0.f, 0.f);
            int gr = row0 + r;
            if (gr < M) v = *(const float4*)(A + (size_t)gr * D_IN + kb + c4 * 4);
            __nv_bfloat16 h0 = __float2bfloat16(v.x);
            __nv_bfloat16 h1 = __float2bfloat16(v.y);
            __nv_bfloat16 h2 = __float2bfloat16(v.z);
            __nv_bfloat16 h3 = __float2bfloat16(v.w);
            __nv_bfloat16 l0 = __float2bfloat16(v.x - __bfloat162float(h0));
            __nv_bfloat16 l1 = __float2bfloat16(v.y - __bfloat162float(h1));
            __nv_bfloat16 l2 = __float2bfloat16(v.z - __bfloat162float(h2));
            __nv_bfloat16 l3 = __float2bfloat16(v.w - __bfloat162float(h3));
            int off = r * LDA + c4 * 4;
            *(uint2*)(As_hi + off) = make_uint2(pk2(h0, h1), pk2(h2, h3));
            *(uint2*)(As_lo + off) = make_uint2(pk2(l0, l1), pk2(l2, l3));
        }
        // stage B chunk [64 x 128] (1024 8-elem groups, 2 iters)
#pragma unroll
        for (int it = 0; it < 2; it++) {
            int g = it * 512 + tid;
            int k = g >> 4, n8 = g & 15;
            int src = (kb + k) * H_DIM + n8 * 8;
            int off = k * LDB + n8 * 8;
            *(uint4*)(Bs_hi + off) = *(const uint4*)(g_wh + src);
            *(uint4*)(Bs_lo + off) = *(const uint4*)(g_wl + src);
        }
        __syncthreads();

#pragma unroll
        for (int kk = 0; kk < 4; kk++) {
            wmma::fragment<wmma::matrix_a, 16, 16, 16, __nv_bfloat16,
                           wmma::row_major> a_hi[2], a_lo[2];
            wmma::fragment<wmma::matrix_b, 16, 16, 16, __nv_bfloat16,
                           wmma::row_major> b_hi[2], b_lo[2];
#pragma unroll
            for (int i = 0; i < 2; i++) {
                const __nv_bfloat16* ap = As_hi + (wm * 32 + i * 16) * LDA + kk * 16;
                wmma::load_matrix_sync(a_hi[i], ap, LDA);
                wmma::load_matrix_sync(a_lo[i], ap + (SM_ALO - SM_AHI) / 2, LDA);
            }
#pragma unroll
            for (int j = 0; j < 2; j++) {
                const __nv_bfloat16* bp = Bs_hi + (kk * 16) * LDB + wn * 32 + j * 16;
                wmma::load_matrix_sync(b_hi[j], bp, LDB);
                wmma::load_matrix_sync(b_lo[j], bp + (SM_BLO - SM_BHI) / 2, LDB);
            }
#pragma unroll
            for (int i = 0; i < 2; i++)
#pragma unroll
                for (int j = 0; j < 2; j++) {
                    wmma::mma_sync(acc[i][j], a_hi[i], b_hi[j], acc[i][j]);
                    wmma::mma_sync(acc[i][j], a_hi[i], b_lo[j], acc[i][j]);
                    wmma::mma_sync(acc[i][j], a_lo[i], b_hi[j], acc[i][j]);
                }
        }
        __syncthreads();
    }

    // epilogue: stage fp32 accs in smem, then coalesced fp16 write
    float* smc = (float*)sm;
#pragma unroll
    for (int i = 0; i < 2; i++)
#pragma unroll
        for (int j = 0; j < 2; j++)
            wmma::store_matrix_sync(smc + (wm * 32 + i * 16) * LDC + wn * 32 + j * 16,
                                    acc[i][j], LDC, wmma::mem_row_major);
    __syncthreads();
#pragma unroll
    for (int it = 0; it < 8; it++) {
        int idx = it * 512 + tid;           // float4 index: 128 rows x 32
        int r = idx >> 5, q = idx & 31;
        float4 v = *(float4*)(smc + r * LDC + q * 4);
        __half2 h0 = __floats2half2_rn(v.x, v.y);
        __half2 h1 = __floats2half2_rn(v.z, v.w);
        *(uint2*)(g_xh + (size_t)(row0 + r) * H_DIM + q * 4) =
            make_uint2(*(uint32_t*)&h0, *(uint32_t*)&h1);
    }
}

// ---------------- fused layer-1 aggregate + relu + W2 dot (fp16 gather) ----
__global__ __launch_bounds__(256) void k_fused1(const float* __restrict__ b1,
                                                const float* __restrict__ W2,
                                                int N) {
    int gid  = blockIdx.x * blockDim.x + threadIdx.x;
    int v    = gid >> 5;
    int lane = gid & 31;
    if (v >= N) return;
    int beg = g_rowptr[v], end = g_rowptr[v + 1];
    int q = lane * 4;
    float4 acc = make_float4(0.f, 0.f, 0.f, 0.f);
    for (int j = beg; j < end; j++) {
        int   src = g_ssrc[j];
        float c   = g_coef[j];
        uint2 u = *(const uint2*)(g_xh + (size_t)src * H_DIM + q);
        float2 f0 = __half22float2(*(__half2*)&u.x);
        float2 f1 = __half22float2(*(__half2*)&u.y);
        acc.x = fmaf(c, f0.x, acc.x);
        acc.y = fmaf(c, f0.y, acc.y);
        acc.z = fmaf(c, f1.x, acc.z);
        acc.w = fmaf(c, f1.y, acc.w);
    }
    float d  = g_dinv[v];
    float d2 = d * d;
    uint2 su = *(const uint2*)(g_xh + (size_t)v * H_DIM + q);
    float2 s0 = __half22float2(*(__half2*)&su.x);
    float2 s1 = __half22float2(*(__half2*)&su.y);
    float4 bb = *(const float4*)&b1[q];
    float4 w  = *(const float4*)&W2[q];
    float sum = fmaxf(d * acc.x + d2 * s0.x + bb.x, 0.f) * w.x
              + fmaxf(d * acc.y + d2 * s0.y + bb.y, 0.f) * w.y
              + fmaxf(d * acc.z + d2 * s1.x + bb.z, 0.f) * w.z
              + fmaxf(d * acc.w + d2 * s1.y + bb.w, 0.f) * w.w;
#pragma unroll
    for (int off = 16; off; off >>= 1)
        sum += __shfl_xor_sync(0xffffffffu, sum, off);
    if (lane == 0) g_s[v] = sum;
}

// ---------------- layer-2 ---------------------------------------------------
__global__ __launch_bounds__(256) void k_out(const float* __restrict__ b2,
                                             float* __restrict__ out, int N) {
    int gid  = blockIdx.x * blockDim.x + threadIdx.x;
    int v    = gid >> 5;
    int lane = gid & 31;
    if (v >= N) return;
    int beg = g_rowptr[v], end = g_rowptr[v + 1];
    float acc = 0.f;
    for (int j = beg + lane; j < end; j += 32)
        acc += g_coef[j] * g_s[g_ssrc[j]];
#pragma unroll
    for (int off = 16; off; off >>= 1)
        acc += __shfl_xor_sync(0xffffffffu, acc, off);
    if (lane == 0) {
        float d = g_dinv[v];
        out[v] = d * acc + d * d * g_s[v] + b2[0];
    }
}

// ---------------- launch ----------------------------------------------------
extern "C" void kernel_launch(void* const* d_in, const int* in_sizes, int n_in,
                              void* d_out, int out_size) {
    const float* x  = (const float*)d_in[0];
    const void*  ei = d_in[1];
    const float* W1 = (const float*)d_in[2];
    const float* b1 = (const float*)d_in[3];
    const float* W2 = (const float*)d_in[4];
    const float* b2 = (const float*)d_in[5];
    float* out = (float*)d_out;

    int N = in_sizes[0] / D_IN;
    int E = in_sizes[1] / 2;
    int nb = (N + 1023) / 1024;

    static int smem_set = 0;
    if (!smem_set) {
        cudaFuncSetAttribute(k_gemm, cudaFuncAttributeMaxDynamicSharedMemorySize,
                             SM_TOTAL);
        smem_set = 1;
    }

    k_detect<<<1, 32>>>((const int*)ei);
    k_prep_w<<<(D_IN * H_DIM + 255) / 256, 256>>>(W1);
    k_zero_deg<<<(N + 255) / 256, 256>>>(N);
    k_gemm<<<(N + 127) / 128, 512, SM_TOTAL>>>(x, N);
    k_hist<<<(E + 255) / 256, 256>>>(ei, E);
    k_dinv<<<(N + 255) / 256, 256>>>(N);
    k_scan1<<<nb, 256>>>(N);
    k_scan2<<<1, 128>>>(nb, N);
    k_scan3<<<(N + 255) / 256, 256>>>(N);
    k_scatter<<<(E + 255) / 256, 256>>>(ei, E);
    k_fused1<<<(N * 32 + 255) / 256, 256>>>(b1, W2, N);
    k_out<<<(N * 32 + 255) / 256, 256>>>(b2, out, N);
}

// round 13
// speedup vs baseline: 2.4680x; 1.1775x over previous
#include <cuda_runtime.h>
#include <cuda_bf16.h>
#include <cuda_fp16.h>
#include <mma.h>
#include <cstdint>

using namespace nvcuda;

#define N_MAX 100000
#define N_PAD 100096              // = 391 * 256, multiple of CTA row tile
#define E_MAX 1600000
#define D_IN  256
#define H_DIM 128

// ---------------- scratch ---------------------------------------------------
__device__ __half g_xh [(size_t)N_PAD * H_DIM];   // x @ W1 (fp16, 25.6 MB)
__device__ float g_dinv[N_MAX];
__device__ int   g_deg [N_MAX];
__device__ int   g_rowptr[N_MAX + 1];
__device__ int   g_cur [N_MAX];
__device__ int   g_part[256];
__device__ int2  g_edge[E_MAX];                   // {src, bitcast coef}
__device__ float g_s   [N_MAX];
__device__ int   g_is64;
__device__ __align__(16) __nv_bfloat16 g_wh[D_IN * H_DIM];  // W1 hi, [k][n]
__device__ __align__(16) __nv_bfloat16 g_wl[D_IN * H_DIM];  // W1 lo, [k][n]

// ---------------- edge dtype detection -------------------------------------
__global__ void k_detect(const int* __restrict__ ei_words) {
    if (threadIdx.x == 0) {
        int is64 = 1;
        for (int i = 1; i < 128; i += 2)
            if (ei_words[i] != 0) { is64 = 0; break; }
        g_is64 = is64;
    }
}
__device__ __forceinline__ int load_edge(const void* ei, int is64, size_t idx) {
    if (is64) return (int)((const long long*)ei)[idx];
    return ((const int*)ei)[idx];
}

// ---------------- W1 bf16 hi/lo split (native k x n layout) ----------------
__global__ void k_prep_w(const float* __restrict__ W1) {
    int i = blockIdx.x * blockDim.x + threadIdx.x;
    if (i >= D_IN * H_DIM) return;
    float v = W1[i];
    __nv_bfloat16 h = __float2bfloat16(v);
    g_wh[i] = h;
    g_wl[i] = __float2bfloat16(v - __bfloat162float(h));
}

// ---------------- degree / norm --------------------------------------------
__global__ void k_zero_deg(int N) {
    int i = blockIdx.x * blockDim.x + threadIdx.x;
    if (i < N) g_deg[i] = 0;
}
__global__ void k_hist(const void* __restrict__ ei, int E) {
    int e = blockIdx.x * blockDim.x + threadIdx.x;
    if (e < E) atomicAdd(&g_deg[load_edge(ei, g_is64, (size_t)E + e)], 1);
}
__global__ void k_dinv(int N) {
    int i = blockIdx.x * blockDim.x + threadIdx.x;
    if (i < N) g_dinv[i] = rsqrtf((float)(g_deg[i] + 1));
}

// ---------------- multi-block scan -----------------------------------------
__global__ void k_scan1(int N) {
    __shared__ int sh[256];
    int b = blockIdx.x, t = threadIdx.x;
    int i0 = b * 1024 + t * 4;
    int v0 = (i0 + 0 < N) ? g_deg[i0 + 0] : 0;
    int v1 = (i0 + 1 < N) ? g_deg[i0 + 1] : 0;
    int v2 = (i0 + 2 < N) ? g_deg[i0 + 2] : 0;
    int v3 = (i0 + 3 < N) ? g_deg[i0 + 3] : 0;
    int s = v0 + v1 + v2 + v3;
    sh[t] = s;
    __syncthreads();
#pragma unroll
    for (int off = 1; off < 256; off <<= 1) {
        int add = (t >= off) ? sh[t - off] : 0;
        __syncthreads();
        sh[t] += add;
        __syncthreads();
    }
    int excl = sh[t] - s;
    if (i0 + 0 < N) { g_rowptr[i0 + 0] = excl; excl += v0; }
    if (i0 + 1 < N) { g_rowptr[i0 + 1] = excl; excl += v1; }
    if (i0 + 2 < N) { g_rowptr[i0 + 2] = excl; excl += v2; }
    if (i0 + 3 < N) { g_rowptr[i0 + 3] = excl; }
    if (t == 255) g_part[b] = sh[255];
}
__global__ void k_scan2(int nb, int N) {
    __shared__ int sh[128];
    int t = threadIdx.x;
    int v = (t < nb) ? g_part[t] : 0;
    sh[t] = v;
    __syncthreads();
#pragma unroll
    for (int off = 1; off < 128; off <<= 1) {
        int add = (t >= off) ? sh[t - off] : 0;
        __syncthreads();
        sh[t] += add;
        __syncthreads();
    }
    if (t < nb) g_part[t] = sh[t] - v;
    if (t == 127) g_rowptr[N] = sh[127];
}
__global__ void k_scan3(int N) {
    int i = blockIdx.x * blockDim.x + threadIdx.x;
    if (i < N) {
        int r = g_rowptr[i] + g_part[i >> 10];
        g_rowptr[i] = r;
        g_cur[i] = r;
    }
}

// ---------------- counting-sort scatter (packed edge) ----------------------
__global__ void k_scatter(const void* __restrict__ ei, int E) {
    int e = blockIdx.x * blockDim.x + threadIdx.x;
    if (e >= E) return;
    int is64 = g_is64;
    int src = load_edge(ei, is64, (size_t)e);
    int dst = load_edge(ei, is64, (size_t)E + e);
    int pos = atomicAdd(&g_cur[dst], 1);
    g_edge[pos] = make_int2(src, __float_as_int(g_dinv[src]));
}

// ---------------- wmma bf16-split GEMM: g_xh = fp16(x @ W1) ----------------
// CTA tile 256x128, 256 threads = 8 warps in 4x2; warp tile 64x64.
// 170 B smem per MMA (vs 341 at 32x32) -> smem-crossbar pressure halved.
// Splits: hi*hi + hi*lo + lo*hi (fp32 accum); lo*lo dropped (~2^-18).
#define LDA 72      // 64 + 8 pad (bf16 elems)
#define LDB 136     // 128 + 8 pad
#define LDC 132     // 128 + 4 pad (fp32 elems, epilogue staging)
#define SM_AHI 0
#define SM_ALO (SM_AHI + 256 * LDA * 2)            // 36864
#define SM_BHI (SM_ALO + 256 * LDA * 2)            // 73728
#define SM_BLO (SM_BHI + 64 * LDB * 2)             // 91136
#define SM_TOTAL (SM_BLO + 64 * LDB * 2)           // 108544

__device__ __forceinline__ uint32_t pk2(__nv_bfloat16 a, __nv_bfloat16 b) {
    __nv_bfloat162 t(a, b);
    return *(uint32_t*)&t;
}

__global__ __launch_bounds__(256) void k_gemm(const float* __restrict__ A, int M) {
    extern __shared__ char sm[];
    __nv_bfloat16* As_hi = (__nv_bfloat16*)(sm + SM_AHI);
    __nv_bfloat16* As_lo = (__nv_bfloat16*)(sm + SM_ALO);
    __nv_bfloat16* Bs_hi = (__nv_bfloat16*)(sm + SM_BHI);
    __nv_bfloat16* Bs_lo = (__nv_bfloat16*)(sm + SM_BLO);

    int tid = threadIdx.x;
    int wid = tid >> 5;
    int wm = wid >> 1;          // 0..3 -> 64-row slab
    int wn = wid & 1;           // 0..1 -> 64-col slab
    int row0 = blockIdx.x * 256;

    wmma::fragment<wmma::accumulator, 16, 16, 16, float> acc[4][4];
#pragma unroll
    for (int i = 0; i < 4; i++)
#pragma unroll
        for (int j = 0; j < 4; j++) wmma::fill_fragment(acc[i][j], 0.0f);

    for (int c = 0; c < 4; c++) {
        int kb = c * 64;
        // stage A chunk [256 x 64] fp32 -> bf16 hi/lo  (4096 float4, 16 iters)
#pragma unroll
        for (int it = 0; it < 16; it++) {
            int f = it * 256 + tid;
            int r = f >> 4, c4 = f & 15;
            float4 v = make_float4(0.f, 0.f, 0.f, 0.f);
            int gr = row0 + r;
            if (gr < M) v = *(const float4*)(A + (size_t)gr * D_IN + kb + c4 * 4);
            __nv_bfloat16 h0 = __float2bfloat16(v.x);
            __nv_bfloat16 h1 = __float2bfloat16(v.y);
            __nv_bfloat16 h2 = __float2bfloat16(v.z);
            __nv_bfloat16 h3 = __float2bfloat16(v.w);
            __nv_bfloat16 l0 = __float2bfloat16(v.x - __bfloat162float(h0));
            __nv_bfloat16 l1 = __float2bfloat16(v.y - __bfloat162float(h1));
            __nv_bfloat16 l2 = __float2bfloat16(v.z - __bfloat162float(h2));
            __nv_bfloat16 l3 = __float2bfloat16(v.w - __bfloat162float(h3));
            int off = r * LDA + c4 * 4;
            *(uint2*)(As_hi + off) = make_uint2(pk2(h0, h1), pk2(h2, h3));
            *(uint2*)(As_lo + off) = make_uint2(pk2(l0, l1), pk2(l2, l3));
        }
        // stage B chunk [64 x 128] (1024 8-elem groups, 4 iters)
#pragma unroll
        for (int it = 0; it < 4; it++) {
            int g = it * 256 + tid;
            int k = g >> 4, n8 = g & 15;
            int src = (kb + k) * H_DIM + n8 * 8;
            int off = k * LDB + n8 * 8;
            *(uint4*)(Bs_hi + off) = *(const uint4*)(g_wh + src);
            *(uint4*)(Bs_lo + off) = *(const uint4*)(g_wl + src);
        }
        __syncthreads();

#pragma unroll
        for (int kk = 0; kk < 4; kk++) {
            wmma::fragment<wmma::matrix_a, 16, 16, 16, __nv_bfloat16,
                           wmma::row_major> a_hi[4], a_lo[4];
#pragma unroll
            for (int i = 0; i < 4; i++) {
                int aoff = (wm * 64 + i * 16) * LDA + kk * 16;
                wmma::load_matrix_sync(a_hi[i], As_hi + aoff, LDA);
                wmma::load_matrix_sync(a_lo[i], As_lo + aoff, LDA);
            }
#pragma unroll
            for (int j = 0; j < 4; j++) {
                wmma::fragment<wmma::matrix_b, 16, 16, 16, __nv_bfloat16,
                               wmma::row_major> b_hi, b_lo;
                int boff = (kk * 16) * LDB + wn * 64 + j * 16;
                wmma::load_matrix_sync(b_hi, Bs_hi + boff, LDB);
                wmma::load_matrix_sync(b_lo, Bs_lo + boff, LDB);
#pragma unroll
                for (int i = 0; i < 4; i++) {
                    wmma::mma_sync(acc[i][j], a_hi[i], b_hi, acc[i][j]);
                    wmma::mma_sync(acc[i][j], a_hi[i], b_lo, acc[i][j]);
                    wmma::mma_sync(acc[i][j], a_lo[i], b_hi, acc[i][j]);
                }
            }
        }
        __syncthreads();
    }

    // epilogue: two passes of 128 rows through smem, coalesced fp16 writes
    float* smc = (float*)sm;
#pragma unroll
    for (int p = 0; p < 2; p++) {
        if ((wm >> 1) == p) {
#pragma unroll
            for (int i = 0; i < 4; i++)
#pragma unroll
                for (int j = 0; j < 4; j++)
                    wmma::store_matrix_sync(
                        smc + ((wm & 1) * 64 + i * 16) * LDC + wn * 64 + j * 16,
                        acc[i][j], LDC, wmma::mem_row_major);
        }
        __syncthreads();
#pragma unroll
        for (int it = 0; it < 16; it++) {
            int idx = it * 256 + tid;        // float4 index: 128 rows x 32
            int r = idx >> 5, q = idx & 31;
            float4 v = *(float4*)(smc + r * LDC + q * 4);
            __half2 h0 = __floats2half2_rn(v.x, v.y);
            __half2 h1 = __floats2half2_rn(v.z, v.w);
            *(uint2*)(g_xh + (size_t)(row0 + p * 128 + r) * H_DIM + q * 4) =
                make_uint2(*(uint32_t*)&h0, *(uint32_t*)&h1);
        }
        __syncthreads();
    }
}

// ---------------- fused layer-1 aggregate + relu + W2 dot (fp16 gather) ----
__global__ __launch_bounds__(256) void k_fused1(const float* __restrict__ b1,
                                                const float* __restrict__ W2,
                                                int N) {
    int gid  = blockIdx.x * blockDim.x + threadIdx.x;
    int v    = gid >> 5;
    int lane = gid & 31;
    if (v >= N) return;
    int beg = g_rowptr[v], end = g_rowptr[v + 1];
    int q = lane * 4;
    float4 acc = make_float4(0.f, 0.f, 0.f, 0.f);
    for (int j = beg; j < end; j++) {
        int2 ec = g_edge[j];
        float c = __int_as_float(ec.y);
        uint2 u = *(const uint2*)(g_xh + (size_t)ec.x * H_DIM + q);
        float2 f0 = __half22float2(*(__half2*)&u.x);
        float2 f1 = __half22float2(*(__half2*)&u.y);
        acc.x = fmaf(c, f0.x, acc.x);
        acc.y = fmaf(c, f0.y, acc.y);
        acc.z = fmaf(c, f1.x, acc.z);
        acc.w = fmaf(c, f1.y, acc.w);
    }
    float d  = g_dinv[v];
    float d2 = d * d;
    uint2 su = *(const uint2*)(g_xh + (size_t)v * H_DIM + q);
    float2 s0 = __half22float2(*(__half2*)&su.x);
    float2 s1 = __half22float2(*(__half2*)&su.y);
    float4 bb = *(const float4*)&b1[q];
    float4 w  = *(const float4*)&W2[q];
    float sum = fmaxf(d * acc.x + d2 * s0.x + bb.x, 0.f) * w.x
              + fmaxf(d * acc.y + d2 * s0.y + bb.y, 0.f) * w.y
              + fmaxf(d * acc.z + d2 * s1.x + bb.z, 0.f) * w.z
              + fmaxf(d * acc.w + d2 * s1.y + bb.w, 0.f) * w.w;
#pragma unroll
    for (int off = 16; off; off >>= 1)
        sum += __shfl_xor_sync(0xffffffffu, sum, off);
    if (lane == 0) g_s[v] = sum;
}

// ---------------- layer-2 ---------------------------------------------------
__global__ __launch_bounds__(256) void k_out(const float* __restrict__ b2,
                                             float* __restrict__ out, int N) {
    int gid  = blockIdx.x * blockDim.x + threadIdx.x;
    int v    = gid >> 5;
    int lane = gid & 31;
    if (v >= N) return;
    int beg = g_rowptr[v], end = g_rowptr[v + 1];
    float acc = 0.f;
    for (int j = beg + lane; j < end; j += 32) {
        int2 ec = g_edge[j];
        acc += __int_as_float(ec.y) * g_s[ec.x];
    }
#pragma unroll
    for (int off = 16; off; off >>= 1)
        acc += __shfl_xor_sync(0xffffffffu, acc, off);
    if (lane == 0) {
        float d = g_dinv[v];
        out[v] = d * acc + d * d * g_s[v] + b2[0];
    }
}

// ---------------- launch ----------------------------------------------------
extern "C" void kernel_launch(void* const* d_in, const int* in_sizes, int n_in,
                              void* d_out, int out_size) {
    const float* x  = (const float*)d_in[0];
    const void*  ei = d_in[1];
    const float* W1 = (const float*)d_in[2];
    const float* b1 = (const float*)d_in[3];
    const float* W2 = (const float*)d_in[4];
    const float* b2 = (const float*)d_in[5];
    float* out = (float*)d_out;

    int N = in_sizes[0] / D_IN;
    int E = in_sizes[1] / 2;
    int nb = (N + 1023) / 1024;

    static cudaStream_t s2;
    static cudaEvent_t evFork, evJoin;
    static int inited = 0;
    if (!inited) {
        cudaFuncSetAttribute(k_gemm, cudaFuncAttributeMaxDynamicSharedMemorySize,
                             SM_TOTAL);
        cudaStreamCreateWithFlags(&s2, cudaStreamNonBlocking);
        cudaEventCreateWithFlags(&evFork, cudaEventDisableTiming);
        cudaEventCreateWithFlags(&evJoin, cudaEventDisableTiming);
        inited = 1;
    }

    // main stream: dtype detect + weight prep + GEMM
    k_detect<<<1, 32>>>((const int*)ei);
    cudaEventRecord(evFork, 0);
    k_prep_w<<<(D_IN * H_DIM + 255) / 256, 256>>>(W1);

    // side stream: CSR build (independent of GEMM)
    cudaStreamWaitEvent(s2, evFork, 0);
    k_zero_deg<<<(N + 255) / 256, 256, 0, s2>>>(N);
    k_hist<<<(E + 255) / 256, 256, 0, s2>>>(ei, E);
    k_dinv<<<(N + 255) / 256, 256, 0, s2>>>(N);
    k_scan1<<<nb, 256, 0, s2>>>(N);
    k_scan2<<<1, 128, 0, s2>>>(nb, N);
    k_scan3<<<(N + 255) / 256, 256, 0, s2>>>(N);
    k_scatter<<<(E + 255) / 256, 256, 0, s2>>>(ei, E);
    cudaEventRecord(evJoin, s2);

    k_gemm<<<(N + 255) / 256, 256, SM_TOTAL>>>(x, N);

    // join, then dependent phase
    cudaStreamWaitEvent(0, evJoin, 0);
    k_fused1<<<(N * 32 + 255) / 256, 256>>>(b1, W2, N);
    k_out<<<(N * 32 + 255) / 256, 256>>>(b2, out, N);
}